// round 5
// baseline (speedup 1.0000x reference)
#include <cuda_runtime.h>

#define ALPHA 0.2f
#define PS_STRIDE 68
#define WH_STRIDE 68

// ---------------- persistent scratch ----------------
__device__ float g_WhH[4 * 4096 * 64];
__device__ float g_WhO[4096 * 64];
__device__ float g_xres[4096 * 64];
__device__ float g_hcat[4096 * 256];
__device__ float g_part[4 * 4096 * 64];   // mode-1 partial numerators (4 j-slices)
__device__ float g_denp[4 * 4096];        // mode-1 partial denominators
__device__ float g_s[5 * 4096];
__device__ float g_t[5 * 4096];

// ---------------- helpers ----------------
__device__ __forceinline__ float elu1(float v) {
    return v > 0.f ? v : (__expf(v) - 1.f);
}
__device__ __forceinline__ float scorep(float sv, float tv, int m) {
    float e = sv + tv;
    e = e > 0.f ? e : ALPHA * e;
    return m > 0 ? __expf(e) : 0.f;
}
__device__ __forceinline__ unsigned long long pk2(float a) {
    unsigned long long r;
    unsigned int b = __float_as_uint(a);
    asm("mov.b64 %0, {%1, %1};" : "=l"(r) : "r"(b));
    return r;
}
__device__ __forceinline__ void ffma2(unsigned long long& d, unsigned long long a,
                                      unsigned long long b) {
    asm("fma.rn.f32x2 %0, %1, %2, %0;" : "+l"(d) : "l"(a), "l"(b));
}
__device__ __forceinline__ float2 upk(unsigned long long v) {
    unsigned int lo, hi;
    asm("mov.b64 {%0, %1}, %2;" : "=r"(lo), "=r"(hi) : "l"(v));
    return make_float2(__uint_as_float(lo), __uint_as_float(hi));
}
__device__ __forceinline__ void cp16(const void* smem_dst, const void* gsrc) {
    unsigned d = (unsigned)__cvta_generic_to_shared(smem_dst);
    asm volatile("cp.async.cg.shared.global [%0], [%1], 16;" :: "r"(d), "l"(gsrc));
}

// ---------------- Kernel A: Wh for 4 heads + x_residual + per-head s,t ----------------
__global__ __launch_bounds__(256) void kA(const float* __restrict__ x,
                                          const float* __restrict__ w_heads,
                                          const float* __restrict__ lin_w,
                                          const float* __restrict__ lin_b,
                                          const float* __restrict__ a_heads) {
    __shared__ float xs[32 * 132];
    __shared__ float ws[64 * 68];
    __shared__ float as_[4 * 128];
    const int tid = threadIdx.x;
    const int i0 = blockIdx.x * 32;

#pragma unroll
    for (int u = 0; u < 16; u++) {
        int idx = tid + 256 * u;
        int r = idx >> 7, f = idx & 127;
        xs[r * 132 + f] = x[(i0 + r) * 128 + f];
    }
#pragma unroll
    for (int u = 0; u < 2; u++) {
        int idx = tid + 256 * u;
        as_[idx] = a_heads[idx];
    }

    const int r = tid >> 3, g = tid & 7;

    for (int cc = 0; cc < 5; cc++) {
        float acc[8];
#pragma unroll
        for (int u = 0; u < 8; u++) acc[u] = 0.f;

        for (int fh = 0; fh < 2; fh++) {
            __syncthreads();
            if (cc < 4) {
#pragma unroll
                for (int u = 0; u < 4; u++) {
                    int f4 = tid + 256 * u;
                    int jj = f4 >> 4, kq = (f4 & 15) * 4;
                    *(float4*)&ws[jj * 68 + kq] =
                        *(const float4*)&w_heads[(cc * 128 + fh * 64 + jj) * 64 + kq];
                }
            } else {
#pragma unroll
                for (int u = 0; u < 16; u++) {
                    int idx = tid + 256 * u;
                    int k = idx >> 6, fo = idx & 63;
                    ws[fo * 68 + k] = lin_w[k * 128 + fh * 64 + fo];
                }
            }
            __syncthreads();
#pragma unroll 8
            for (int fo = 0; fo < 64; fo++) {
                float xv = xs[r * 132 + fh * 64 + fo];
                float4 w0 = *(float4*)&ws[fo * 68 + g * 4];
                float4 w1 = *(float4*)&ws[fo * 68 + 32 + g * 4];
                acc[0] += xv * w0.x; acc[1] += xv * w0.y;
                acc[2] += xv * w0.z; acc[3] += xv * w0.w;
                acc[4] += xv * w1.x; acc[5] += xv * w1.y;
                acc[6] += xv * w1.z; acc[7] += xv * w1.w;
            }
        }

        if (cc < 4) {
            float* dst = g_WhH + ((size_t)(cc * 4096) + i0 + r) * 64;
            *(float4*)(dst + g * 4) = make_float4(acc[0], acc[1], acc[2], acc[3]);
            *(float4*)(dst + 32 + g * 4) = make_float4(acc[4], acc[5], acc[6], acc[7]);
            // fused s,t: dot with a_heads[cc]
            const float* av = as_ + cc * 128;
            float sp = 0.f, tp = 0.f;
#pragma unroll
            for (int u = 0; u < 4; u++) {
                int c0 = g * 4 + u, c1 = 32 + g * 4 + u;
                sp += acc[u] * av[c0] + acc[4 + u] * av[c1];
                tp += acc[u] * av[64 + c0] + acc[4 + u] * av[64 + c1];
            }
            sp += __shfl_xor_sync(0xffffffffu, sp, 1);
            sp += __shfl_xor_sync(0xffffffffu, sp, 2);
            sp += __shfl_xor_sync(0xffffffffu, sp, 4);
            tp += __shfl_xor_sync(0xffffffffu, tp, 1);
            tp += __shfl_xor_sync(0xffffffffu, tp, 2);
            tp += __shfl_xor_sync(0xffffffffu, tp, 4);
            if (g == 0) {
                g_s[cc * 4096 + i0 + r] = sp;
                g_t[cc * 4096 + i0 + r] = tp;
            }
        } else {
            float* dst = g_xres + ((size_t)(i0 + r)) * 64;
            float4 oa = make_float4(acc[0] + lin_b[g * 4 + 0], acc[1] + lin_b[g * 4 + 1],
                                    acc[2] + lin_b[g * 4 + 2], acc[3] + lin_b[g * 4 + 3]);
            float4 ob = make_float4(acc[4] + lin_b[32 + g * 4 + 0], acc[5] + lin_b[32 + g * 4 + 1],
                                    acc[6] + lin_b[32 + g * 4 + 2], acc[7] + lin_b[32 + g * 4 + 3]);
            *(float4*)(dst + g * 4) = oa;
            *(float4*)(dst + 32 + g * 4) = ob;
        }
    }
}

// ---------------- Kernel C: fused masked-softmax aggregation, 128-row tiles, pipelined ----------------
// mode 0: blockIdx.y = head, full j-range, write elu -> g_hcat
// mode 1: blockIdx.y = j-slice (1024 wide), write raw partials -> g_part/g_denp
extern __shared__ float smemC[];

__global__ __launch_bounds__(256, 1) void kC(const int* __restrict__ adj, int mode) {
    float* whs = smemC;                          // 2 * 64 * 68
    float* Ps  = smemC + 2 * 64 * WH_STRIDE;     // 2 * 128 * 68
    float* dh  = Ps + 2 * 128 * PS_STRIDE;       // 256

    const int tid = threadIdx.x;
    const int i0 = blockIdx.x * 128;

    const float *Wh, *sh, *th;
    int jlo, T, hb = 0, sl = 0;
    if (mode == 0) {
        hb = blockIdx.y;
        Wh = g_WhH + (size_t)hb * 4096 * 64;
        sh = g_s + hb * 4096;
        th = g_t + hb * 4096;
        jlo = 0; T = 64;
    } else {
        sl = blockIdx.y;
        Wh = g_WhO;
        sh = g_s + 4 * 4096;
        th = g_t + 4 * 4096;
        jlo = sl * 1024; T = 16;
    }

    // phase-1 mapping: 2 threads per row
    const int r2 = tid >> 1, half = tid & 1;
    const float sv = sh[i0 + r2];
    const int* arow = adj + (size_t)(i0 + r2) * 4096 + half * 32;
    const float* trow = th + half * 32;

    // phase-2 mapping: rows lane+32rr, cols wq*4..+3 and 32+wq*4..+3
    const int lane = tid & 31, wq = tid >> 5;

    unsigned long long acc[16];
#pragma unroll
    for (int u = 0; u < 16; u++) acc[u] = 0ull;
    float dpart = 0.f;

    int4 areg[8];
    float4 treg[8];

    // ---- stage tile 0 (whs via cp.async), prefetch adj/t tile 0 ----
    {
        const int j0 = jlo;
#pragma unroll
        for (int u = 0; u < 4; u++) {
            int c = tid + 256 * u;
            int jj = c >> 4, q = c & 15;
            cp16(whs + jj * WH_STRIDE + q * 4, Wh + (size_t)(j0 + jj) * 64 + q * 4);
        }
        asm volatile("cp.async.commit_group;");
#pragma unroll
        for (int u = 0; u < 8; u++) {
            areg[u] = *(const int4*)(arow + j0 + u * 4);
            treg[u] = *(const float4*)(trow + j0 + u * 4);
        }
        asm volatile("cp.async.wait_group 0;");
        // phase 1 for tile 0
        float dadd = 0.f;
        float* Pd = Ps + r2 * PS_STRIDE + half * 32;
#pragma unroll
        for (int u = 0; u < 8; u++) {
            int4 a = areg[u]; float4 tv = treg[u];
            float4 p;
            p.x = scorep(sv, tv.x, a.x);
            p.y = scorep(sv, tv.y, a.y);
            p.z = scorep(sv, tv.z, a.z);
            p.w = scorep(sv, tv.w, a.w);
            *(float4*)(Pd + u * 4) = p;
            dadd += (p.x + p.y) + (p.z + p.w);
        }
        dpart += dadd;
    }

    for (int t = 0; t < T; t++) {
        const int buf = t & 1, nbuf = 1 - buf;
        if (t + 1 < T) {
            const int j0n = jlo + (t + 1) * 64;
#pragma unroll
            for (int u = 0; u < 4; u++) {
                int c = tid + 256 * u;
                int jj = c >> 4, q = c & 15;
                cp16(whs + nbuf * (64 * WH_STRIDE) + jj * WH_STRIDE + q * 4,
                     Wh + (size_t)(j0n + jj) * 64 + q * 4);
            }
            asm volatile("cp.async.commit_group;");
#pragma unroll
            for (int u = 0; u < 8; u++) {
                areg[u] = *(const int4*)(arow + j0n + u * 4);
                treg[u] = *(const float4*)(trow + j0n + u * 4);
            }
        }
        __syncthreads();

        // ---- phase 2: acc += P[buf] * whs[buf] ----
        const float* Wb = whs + buf * (64 * WH_STRIDE) + wq * 4;
        const float* Pr = Ps + buf * (128 * PS_STRIDE) + lane * PS_STRIDE;
#pragma unroll 4
        for (int q = 0; q < 16; q++) {
            float p0[4], p1[4], p2[4], p3[4];
            *(float4*)p0 = *(const float4*)(Pr + q * 4);
            *(float4*)p1 = *(const float4*)(Pr + 32 * PS_STRIDE + q * 4);
            *(float4*)p2 = *(const float4*)(Pr + 64 * PS_STRIDE + q * 4);
            *(float4*)p3 = *(const float4*)(Pr + 96 * PS_STRIDE + q * 4);
#pragma unroll
            for (int u = 0; u < 4; u++) {
                const float* wr = Wb + (q * 4 + u) * WH_STRIDE;
                ulonglong2 wA = *(const ulonglong2*)wr;
                ulonglong2 wB = *(const ulonglong2*)(wr + 32);
                unsigned long long v0 = pk2(p0[u]);
                ffma2(acc[0], v0, wA.x); ffma2(acc[1], v0, wA.y);
                ffma2(acc[2], v0, wB.x); ffma2(acc[3], v0, wB.y);
                unsigned long long v1 = pk2(p1[u]);
                ffma2(acc[4], v1, wA.x); ffma2(acc[5], v1, wA.y);
                ffma2(acc[6], v1, wB.x); ffma2(acc[7], v1, wB.y);
                unsigned long long v2 = pk2(p2[u]);
                ffma2(acc[8], v2, wA.x); ffma2(acc[9], v2, wA.y);
                ffma2(acc[10], v2, wB.x); ffma2(acc[11], v2, wB.y);
                unsigned long long v3 = pk2(p3[u]);
                ffma2(acc[12], v3, wA.x); ffma2(acc[13], v3, wA.y);
                ffma2(acc[14], v3, wB.x); ffma2(acc[15], v3, wB.y);
            }
        }

        if (t + 1 < T) {
            asm volatile("cp.async.wait_group 0;");
            // ---- phase 1 for tile t+1 ----
            float dadd = 0.f;
            float* Pd = Ps + nbuf * (128 * PS_STRIDE) + r2 * PS_STRIDE + half * 32;
#pragma unroll
            for (int u = 0; u < 8; u++) {
                int4 a = areg[u]; float4 tv = treg[u];
                float4 p;
                p.x = scorep(sv, tv.x, a.x);
                p.y = scorep(sv, tv.y, a.y);
                p.z = scorep(sv, tv.z, a.z);
                p.w = scorep(sv, tv.w, a.w);
                *(float4*)(Pd + u * 4) = p;
                dadd += (p.x + p.y) + (p.z + p.w);
            }
            dpart += dadd;
        }
    }

    // denominators
    dh[tid] = dpart;   // dh[2*row + half]
    __syncthreads();

#pragma unroll
    for (int rr = 0; rr < 4; rr++) {
        int row = lane + rr * 32;
        float dden = dh[2 * row] + dh[2 * row + 1];
        float2 c0 = upk(acc[rr * 4 + 0]);
        float2 c1 = upk(acc[rr * 4 + 1]);
        float2 c2 = upk(acc[rr * 4 + 2]);
        float2 c3 = upk(acc[rr * 4 + 3]);
        if (mode == 0) {
            float dinv = 1.f / dden;
            float* dst = g_hcat + (size_t)(i0 + row) * 256 + hb * 64;
            *(float4*)(dst + wq * 4) =
                make_float4(elu1(c0.x * dinv), elu1(c0.y * dinv),
                            elu1(c1.x * dinv), elu1(c1.y * dinv));
            *(float4*)(dst + 32 + wq * 4) =
                make_float4(elu1(c2.x * dinv), elu1(c2.y * dinv),
                            elu1(c3.x * dinv), elu1(c3.y * dinv));
        } else {
            float* dst = g_part + ((size_t)sl * 4096 + i0 + row) * 64;
            *(float4*)(dst + wq * 4) = make_float4(c0.x, c0.y, c1.x, c1.y);
            *(float4*)(dst + 32 + wq * 4) = make_float4(c2.x, c2.y, c3.x, c3.y);
            if (wq == 0) g_denp[sl * 4096 + i0 + row] = dden;
        }
    }
}

// ---------------- Kernel E: out-layer Wh = hcat @ w_out, plus s,t ----------------
__global__ __launch_bounds__(256) void kE(const float* __restrict__ w_out,
                                          const float* __restrict__ a_out) {
    __shared__ float hc[16 * 260];
    __shared__ float ws[64 * 68];
    const int tid = threadIdx.x;
    const int i0 = blockIdx.x * 16;

#pragma unroll
    for (int u = 0; u < 4; u++) {
        int f4 = tid + 256 * u;
        int r = f4 >> 6, cq = (f4 & 63) * 4;
        *(float4*)&hc[r * 260 + cq] = *(const float4*)&g_hcat[(size_t)(i0 + r) * 256 + cq];
    }

    const int r2 = tid >> 4, g2 = tid & 15;
    float acc[4] = {0.f, 0.f, 0.f, 0.f};

    for (int fc = 0; fc < 4; fc++) {
        __syncthreads();
#pragma unroll
        for (int u = 0; u < 4; u++) {
            int f4 = tid + 256 * u;
            int jj = f4 >> 4, kq = (f4 & 15) * 4;
            *(float4*)&ws[jj * 68 + kq] = *(const float4*)&w_out[(fc * 64 + jj) * 64 + kq];
        }
        __syncthreads();
#pragma unroll 8
        for (int fo = 0; fo < 64; fo++) {
            float xv = hc[r2 * 260 + fc * 64 + fo];
            float4 wv = *(float4*)&ws[fo * 68 + g2 * 4];
            acc[0] += xv * wv.x; acc[1] += xv * wv.y;
            acc[2] += xv * wv.z; acc[3] += xv * wv.w;
        }
    }

    float* dst = g_WhO + (size_t)(i0 + r2) * 64 + g2 * 4;
    *(float4*)dst = make_float4(acc[0], acc[1], acc[2], acc[3]);
    __syncthreads();

    if (tid < 16) {
        const float* wr = g_WhO + (size_t)(i0 + tid) * 64;
        float sAcc = 0.f, tAcc = 0.f;
        for (int k = 0; k < 64; k++) {
            float v = wr[k];
            sAcc += v * a_out[k];
            tAcc += v * a_out[64 + k];
        }
        g_s[4 * 4096 + i0 + tid] = sAcc;
        g_t[4 * 4096 + i0 + tid] = tAcc;
    }
}

// ---------------- Kernel G: combine mode-1 partials + final linear + elu ----------------
__global__ __launch_bounds__(256) void kG(const float* __restrict__ outlin_w,
                                          const float* __restrict__ outlin_b,
                                          float* __restrict__ out) {
    __shared__ float vi[32 * 68];
    __shared__ float wt[64 * 68];
    const int tid = threadIdx.x;
    const int i0 = blockIdx.x * 32;

#pragma unroll
    for (int u = 0; u < 2; u++) {
        int f4 = tid + 256 * u;
        int r = f4 >> 4, kq = (f4 & 15) * 4;
        int row = i0 + r;
        float4 xa = *(const float4*)&g_xres[(size_t)row * 64 + kq];
        float4 n = *(const float4*)&g_part[((size_t)0 * 4096 + row) * 64 + kq];
        float4 n1 = *(const float4*)&g_part[((size_t)1 * 4096 + row) * 64 + kq];
        float4 n2 = *(const float4*)&g_part[((size_t)2 * 4096 + row) * 64 + kq];
        float4 n3 = *(const float4*)&g_part[((size_t)3 * 4096 + row) * 64 + kq];
        n.x += n1.x + n2.x + n3.x;
        n.y += n1.y + n2.y + n3.y;
        n.z += n1.z + n2.z + n3.z;
        n.w += n1.w + n2.w + n3.w;
        float ds = g_denp[row] + g_denp[4096 + row] + g_denp[2 * 4096 + row] +
                   g_denp[3 * 4096 + row];
        float di = 1.f / ds;
        xa.x += elu1(n.x * di);
        xa.y += elu1(n.y * di);
        xa.z += elu1(n.z * di);
        xa.w += elu1(n.w * di);
        *(float4*)&vi[r * 68 + kq] = xa;
    }
#pragma unroll
    for (int u = 0; u < 16; u++) {
        int idx = tid + 256 * u;
        int k2 = idx >> 6, k = idx & 63;
        wt[k * 68 + k2] = outlin_w[k2 * 64 + k];
    }
    __syncthreads();

    const int r = tid >> 3, g = tid & 7;
    float acc[8];
#pragma unroll
    for (int u = 0; u < 8; u++) acc[u] = 0.f;
#pragma unroll 8
    for (int k = 0; k < 64; k++) {
        float xv = vi[r * 68 + k];
        float4 w0 = *(float4*)&wt[k * 68 + g * 4];
        float4 w1 = *(float4*)&wt[k * 68 + 32 + g * 4];
        acc[0] += xv * w0.x; acc[1] += xv * w0.y;
        acc[2] += xv * w0.z; acc[3] += xv * w0.w;
        acc[4] += xv * w1.x; acc[5] += xv * w1.y;
        acc[6] += xv * w1.z; acc[7] += xv * w1.w;
    }
    float* dst = out + (size_t)(i0 + r) * 64;
    float4 oa = make_float4(elu1(acc[0] + outlin_b[g * 4 + 0]),
                            elu1(acc[1] + outlin_b[g * 4 + 1]),
                            elu1(acc[2] + outlin_b[g * 4 + 2]),
                            elu1(acc[3] + outlin_b[g * 4 + 3]));
    float4 ob = make_float4(elu1(acc[4] + outlin_b[32 + g * 4 + 0]),
                            elu1(acc[5] + outlin_b[32 + g * 4 + 1]),
                            elu1(acc[6] + outlin_b[32 + g * 4 + 2]),
                            elu1(acc[7] + outlin_b[32 + g * 4 + 3]));
    *(float4*)(dst + g * 4) = oa;
    *(float4*)(dst + 32 + g * 4) = ob;
}

// ---------------- launch ----------------
extern "C" void kernel_launch(void* const* d_in, const int* in_sizes, int n_in,
                              void* d_out, int out_size) {
    const float* x        = (const float*)d_in[0];
    const int*   adj      = (const int*)d_in[1];
    const float* w_heads  = (const float*)d_in[2];
    const float* a_heads  = (const float*)d_in[3];
    const float* w_out    = (const float*)d_in[4];
    const float* a_out    = (const float*)d_in[5];
    const float* lin_w    = (const float*)d_in[6];
    const float* lin_b    = (const float*)d_in[7];
    const float* outlin_w = (const float*)d_in[8];
    const float* outlin_b = (const float*)d_in[9];
    float* out = (float*)d_out;

    const int SMEM_C = (2 * 64 * WH_STRIDE + 2 * 128 * PS_STRIDE + 256) * 4;
    cudaFuncSetAttribute(kC, cudaFuncAttributeMaxDynamicSharedMemorySize, SMEM_C);

    kA<<<128, 256>>>(x, w_heads, lin_w, lin_b, a_heads);
    kC<<<dim3(32, 4), 256, SMEM_C>>>(adj, 0);   // 4 heads, full j-range -> g_hcat
    kE<<<256, 256>>>(w_out, a_out);             // out-layer Wh + s,t
    kC<<<dim3(32, 4), 256, SMEM_C>>>(adj, 1);   // out layer, 4 j-slices -> partials
    kG<<<128, 256>>>(outlin_w, outlin_b, out);  // combine + final linear + elu
}

// round 10
// speedup vs baseline: 2.5115x; 2.5115x over previous
#include <cuda_runtime.h>
#include <cstdint>

#define ALPHA 0.2f

// ---------------- persistent scratch ----------------
__device__ float    g_Wh[4 * 4096 * 64];     // per-head Wh [head][node][64], tf32-rounded
__device__ float    g_WhO[4096 * 64];        // out-layer Wh, tf32-rounded
__device__ float4   g_sq[5 * 4096];          // (s, e^s, e^{0.2s}, 0)
__device__ float4   g_tq[5 * 4096];          // (t, e^t, e^{0.2t}, 0)
__device__ unsigned g_adjbits[4096 * 128];   // bit-packed adjacency
__device__ float    g_xres[4096 * 64];
__device__ float    g_hcat[4096 * 256];
__device__ float    g_part[4 * 4096 * 64];
__device__ float    g_denp[4 * 4096];

// ---------------- helpers ----------------
__device__ __forceinline__ float elu1(float v) {
    return v > 0.f ? v : (__expf(v) - 1.f);
}
__device__ __forceinline__ void cp16(void* smem_dst, const void* gsrc) {
    unsigned d = (unsigned)__cvta_generic_to_shared(smem_dst);
    asm volatile("cp.async.cg.shared.global [%0], [%1], 16;" :: "r"(d), "l"(gsrc));
}
__device__ __forceinline__ unsigned tf32u(float f) {
    unsigned u;
    asm("cvt.rna.tf32.f32 %0, %1;" : "=r"(u) : "f"(f));
    return u;
}
__device__ __forceinline__ float tf32r(float f) {
    return __uint_as_float(tf32u(f));
}
__device__ __forceinline__ void mma8(float* d, const unsigned* a, unsigned b0, unsigned b1) {
    asm volatile(
        "mma.sync.aligned.m16n8k8.row.col.f32.tf32.tf32.f32 "
        "{%0,%1,%2,%3},{%4,%5,%6,%7},{%8,%9},{%0,%1,%2,%3};"
        : "+f"(d[0]), "+f"(d[1]), "+f"(d[2]), "+f"(d[3])
        : "r"(a[0]), "r"(a[1]), "r"(a[2]), "r"(a[3]), "r"(b0), "r"(b1));
}

// ---------------- kP: bit-pack adjacency ----------------
__global__ __launch_bounds__(256) void kP(const int* __restrict__ adj) {
    const int row = blockIdx.x;
    const int w = threadIdx.x >> 5, lane = threadIdx.x & 31;
    const int* base = adj + (size_t)row * 4096;
#pragma unroll
    for (int it = 0; it < 16; it++) {
        int col = (w * 16 + it) * 32 + lane;
        unsigned m = __ballot_sync(0xffffffffu, base[col] > 0);
        if (lane == 0) g_adjbits[row * 128 + w * 16 + it] = m;
    }
}

// ---------------- kA: per-head Wh (tf32-rounded) + s,t quads + x_residual ----------------
__global__ __launch_bounds__(256) void kA(const float* __restrict__ x,
                                          const float* __restrict__ w_heads,
                                          const float* __restrict__ lin_w,
                                          const float* __restrict__ lin_b,
                                          const float* __restrict__ a_heads) {
    __shared__ float xs[32 * 132];
    __shared__ float ws[64 * 68];
    const int tid = threadIdx.x;
    const int i0 = blockIdx.x * 32;

#pragma unroll
    for (int u = 0; u < 16; u++) {
        int idx = tid + 256 * u;
        int r = idx >> 7, f = idx & 127;
        xs[r * 132 + f] = x[(i0 + r) * 128 + f];
    }

    const int r = tid >> 3, g = tid & 7;

    for (int cc = 0; cc < 5; cc++) {
        float acc[8];
#pragma unroll
        for (int u = 0; u < 8; u++) acc[u] = 0.f;

        for (int fh = 0; fh < 2; fh++) {
            __syncthreads();
            if (cc < 4) {
#pragma unroll
                for (int u = 0; u < 4; u++) {
                    int f4 = tid + 256 * u;
                    int jj = f4 >> 4, kq = (f4 & 15) * 4;
                    *(float4*)&ws[jj * 68 + kq] =
                        *(const float4*)&w_heads[(cc * 128 + fh * 64 + jj) * 64 + kq];
                }
            } else {
#pragma unroll
                for (int u = 0; u < 16; u++) {
                    int idx = tid + 256 * u;
                    int k = idx >> 6, fo = idx & 63;
                    ws[fo * 68 + k] = lin_w[k * 128 + fh * 64 + fo];
                }
            }
            __syncthreads();
#pragma unroll 8
            for (int fo = 0; fo < 64; fo++) {
                float xv = xs[r * 132 + fh * 64 + fo];
                float4 w0 = *(float4*)&ws[fo * 68 + g * 4];
                float4 w1 = *(float4*)&ws[fo * 68 + 32 + g * 4];
                acc[0] += xv * w0.x; acc[1] += xv * w0.y;
                acc[2] += xv * w0.z; acc[3] += xv * w0.w;
                acc[4] += xv * w1.x; acc[5] += xv * w1.y;
                acc[6] += xv * w1.z; acc[7] += xv * w1.w;
            }
        }

        if (cc < 4) {
            // s,t quads from full-precision acc
            const float* av = a_heads + cc * 128;
            float sp = 0.f, tp = 0.f;
#pragma unroll
            for (int u = 0; u < 4; u++) {
                int c0 = g * 4 + u, c1 = 32 + g * 4 + u;
                sp += acc[u] * av[c0] + acc[4 + u] * av[c1];
                tp += acc[u] * av[64 + c0] + acc[4 + u] * av[64 + c1];
            }
            sp += __shfl_xor_sync(0xffffffffu, sp, 1);
            sp += __shfl_xor_sync(0xffffffffu, sp, 2);
            sp += __shfl_xor_sync(0xffffffffu, sp, 4);
            tp += __shfl_xor_sync(0xffffffffu, tp, 1);
            tp += __shfl_xor_sync(0xffffffffu, tp, 2);
            tp += __shfl_xor_sync(0xffffffffu, tp, 4);
            if (g == 0) {
                g_sq[cc * 4096 + i0 + r] = make_float4(sp, __expf(sp), __expf(ALPHA * sp), 0.f);
                g_tq[cc * 4096 + i0 + r] = make_float4(tp, __expf(tp), __expf(ALPHA * tp), 0.f);
            }
            // tf32-rounded store (B operand for kC)
            float* dst = g_Wh + ((size_t)cc * 4096 + i0 + r) * 64;
            *(float4*)(dst + g * 4) =
                make_float4(tf32r(acc[0]), tf32r(acc[1]), tf32r(acc[2]), tf32r(acc[3]));
            *(float4*)(dst + 32 + g * 4) =
                make_float4(tf32r(acc[4]), tf32r(acc[5]), tf32r(acc[6]), tf32r(acc[7]));
        } else {
            float* dst = g_xres + (size_t)(i0 + r) * 64;
            *(float4*)(dst + g * 4) =
                make_float4(acc[0] + lin_b[g * 4 + 0], acc[1] + lin_b[g * 4 + 1],
                            acc[2] + lin_b[g * 4 + 2], acc[3] + lin_b[g * 4 + 3]);
            *(float4*)(dst + 32 + g * 4) =
                make_float4(acc[4] + lin_b[32 + g * 4 + 0], acc[5] + lin_b[32 + g * 4 + 1],
                            acc[6] + lin_b[32 + g * 4 + 2], acc[7] + lin_b[32 + g * 4 + 3]);
        }
    }
}

// ---------------- kC: fused attention via warp-level tf32 mma.sync ----------------
// mode 0: blockIdx.y = head, T=64 tiles -> elu -> g_hcat
// mode 1: blockIdx.y = j-slice (1024 wide), T=16 -> raw partials -> g_part/g_denp
__global__ __launch_bounds__(256) void kC(int mode) {
    __shared__ float  whs[2][64 * 72];   // B tile, j-major, pad 72 (conflict-free frags)
    __shared__ float4 tst[2][64];        // t quads
    __shared__ float  dh[128];           // row denominators

    const int tid = threadIdx.x;
    const int w = tid >> 5, lane = tid & 31;
    const int k = lane & 3, m = lane >> 2;
    const int i0 = blockIdx.x * 128;

    const float* Wh;
    const float4 *tq, *sq;
    int jlo, T, hb = 0, sl = 0;
    if (mode == 0) {
        hb = blockIdx.y;
        Wh = g_Wh + (size_t)hb * 4096 * 64;
        tq = g_tq + hb * 4096;
        sq = g_sq + hb * 4096;
        jlo = 0; T = 64;
    } else {
        sl = blockIdx.y;
        Wh = g_WhO;
        tq = g_tq + 4 * 4096;
        sq = g_sq + 4 * 4096;
        jlo = sl * 1024; T = 16;
    }

    const int rowA = 16 * w + m, rowB = rowA + 8;   // block-local rows
    const float4 sdA = sq[i0 + rowA];
    const float4 sdB = sq[i0 + rowB];
    const unsigned* amA = g_adjbits + (size_t)(i0 + rowA) * 128 + (jlo >> 5);
    const unsigned* amB = g_adjbits + (size_t)(i0 + rowB) * 128 + (jlo >> 5);

    float acc[8][4];
#pragma unroll
    for (int n = 0; n < 8; n++)
#pragma unroll
        for (int u = 0; u < 4; u++) acc[n][u] = 0.f;

    // ---- preload tile 0 ----
#pragma unroll
    for (int u = 0; u < 4; u++) {
        int c = tid + 256 * u;
        int jj = c >> 4, q = c & 15;
        cp16(&whs[0][jj * 72 + q * 4], Wh + (size_t)(jlo + jj) * 64 + q * 4);
    }
    if (tid < 64) cp16(&tst[0][tid], tq + jlo + tid);
    asm volatile("cp.async.commit_group;");
    uint2 mAv = *(const uint2*)amA;
    uint2 mBv = *(const uint2*)amB;
    asm volatile("cp.async.wait_group 0;" ::: "memory");
    __syncthreads();

    float dp0 = 0.f, dp1 = 0.f;

    for (int t = 0; t < T; t++) {
        const int b = t & 1, nb = b ^ 1;

        // prefetch tile t+1
        uint2 mAn, mBn;
        if (t + 1 < T) {
            const int j0n = jlo + (t + 1) * 64;
#pragma unroll
            for (int u = 0; u < 4; u++) {
                int c = tid + 256 * u;
                int jj = c >> 4, q = c & 15;
                cp16(&whs[nb][jj * 72 + q * 4], Wh + (size_t)(j0n + jj) * 64 + q * 4);
            }
            if (tid < 64) cp16(&tst[nb][tid], tq + j0n + tid);
            asm volatile("cp.async.commit_group;");
            mAn = *(const uint2*)(amA + 2 * (t + 1));
            mBn = *(const uint2*)(amB + 2 * (t + 1));
        }

        // ---- phase 1: A fragments in registers ----
        unsigned afr[8][4];
#pragma unroll
        for (int s = 0; s < 8; s++) {
            float4 tv0 = tst[b][8 * s + k];
            float4 tv1 = tst[b][8 * s + k + 4];
            unsigned shA = ((s < 4) ? mAv.x : mAv.y) >> ((8 * s + k) & 31);
            unsigned shB = ((s < 4) ? mBv.x : mBv.y) >> ((8 * s + k) & 31);
            float e, p0, p1, p2, p3;
            e = sdA.x + tv0.x;
            p0 = (shA & 1u) ? ((e > 0.f ? sdA.y : sdA.z) * (e > 0.f ? tv0.y : tv0.z)) : 0.f;
            e = sdB.x + tv0.x;
            p1 = (shB & 1u) ? ((e > 0.f ? sdB.y : sdB.z) * (e > 0.f ? tv0.y : tv0.z)) : 0.f;
            e = sdA.x + tv1.x;
            p2 = ((shA >> 4) & 1u) ? ((e > 0.f ? sdA.y : sdA.z) * (e > 0.f ? tv1.y : tv1.z)) : 0.f;
            e = sdB.x + tv1.x;
            p3 = ((shB >> 4) & 1u) ? ((e > 0.f ? sdB.y : sdB.z) * (e > 0.f ? tv1.y : tv1.z)) : 0.f;
            dp0 += p0 + p2;
            dp1 += p1 + p3;
            afr[s][0] = tf32u(p0);
            afr[s][1] = tf32u(p1);
            afr[s][2] = tf32u(p2);
            afr[s][3] = tf32u(p3);
        }

        // ---- mma: acc += A(P) * B(Wh) ----
        const float* wb = whs[b];
#pragma unroll
        for (int s = 0; s < 8; s++) {
            const float* r0 = wb + (8 * s + k) * 72 + m;
            const float* r1 = r0 + 4 * 72;
#pragma unroll
            for (int n = 0; n < 8; n++) {
                unsigned b0 = __float_as_uint(r0[8 * n]);
                unsigned b1 = __float_as_uint(r1[8 * n]);
                mma8(acc[n], afr[s], b0, b1);
            }
        }

        if (t + 1 < T) {
            asm volatile("cp.async.wait_group 0;" ::: "memory");
            mAv = mAn; mBv = mBn;
        }
        __syncthreads();
    }

    // ---- denominators: reduce over k lanes ----
    dp0 += __shfl_xor_sync(0xffffffffu, dp0, 1);
    dp0 += __shfl_xor_sync(0xffffffffu, dp0, 2);
    dp1 += __shfl_xor_sync(0xffffffffu, dp1, 1);
    dp1 += __shfl_xor_sync(0xffffffffu, dp1, 2);
    if (k == 0) {
        dh[rowA] = dp0;
        dh[rowB] = dp1;
    }
    __syncthreads();

    // ---- epilogue ----
    const float dA = dh[rowA], dB = dh[rowB];
    if (mode == 0) {
        const float iA = 1.f / dA, iB = 1.f / dB;
        float* dstA = g_hcat + (size_t)(i0 + rowA) * 256 + hb * 64 + 2 * k;
        float* dstB = g_hcat + (size_t)(i0 + rowB) * 256 + hb * 64 + 2 * k;
#pragma unroll
        for (int n = 0; n < 8; n++) {
            *(float2*)(dstA + 8 * n) = make_float2(elu1(acc[n][0] * iA), elu1(acc[n][1] * iA));
            *(float2*)(dstB + 8 * n) = make_float2(elu1(acc[n][2] * iB), elu1(acc[n][3] * iB));
        }
    } else {
        float* dstA = g_part + ((size_t)sl * 4096 + i0 + rowA) * 64 + 2 * k;
        float* dstB = g_part + ((size_t)sl * 4096 + i0 + rowB) * 64 + 2 * k;
#pragma unroll
        for (int n = 0; n < 8; n++) {
            *(float2*)(dstA + 8 * n) = make_float2(acc[n][0], acc[n][1]);
            *(float2*)(dstB + 8 * n) = make_float2(acc[n][2], acc[n][3]);
        }
        if (k == 0) {
            g_denp[sl * 4096 + i0 + rowA] = dA;
            g_denp[sl * 4096 + i0 + rowB] = dB;
        }
    }
}

// ---------------- kE: out-layer Wh (tf32-rounded) + s,t quads ----------------
__global__ __launch_bounds__(256) void kE(const float* __restrict__ w_out,
                                          const float* __restrict__ a_out) {
    __shared__ float hc[16 * 260];
    __shared__ float ws[64 * 68];
    const int tid = threadIdx.x;
    const int i0 = blockIdx.x * 16;

#pragma unroll
    for (int u = 0; u < 4; u++) {
        int f4 = tid + 256 * u;
        int r = f4 >> 6, cq = (f4 & 63) * 4;
        *(float4*)&hc[r * 260 + cq] = *(const float4*)&g_hcat[(size_t)(i0 + r) * 256 + cq];
    }

    const int r2 = tid >> 4, g2 = tid & 15;
    float acc[4] = {0.f, 0.f, 0.f, 0.f};

    for (int fc = 0; fc < 4; fc++) {
        __syncthreads();
#pragma unroll
        for (int u = 0; u < 4; u++) {
            int f4 = tid + 256 * u;
            int jj = f4 >> 4, kq = (f4 & 15) * 4;
            *(float4*)&ws[jj * 68 + kq] = *(const float4*)&w_out[(fc * 64 + jj) * 64 + kq];
        }
        __syncthreads();
#pragma unroll 8
        for (int fo = 0; fo < 64; fo++) {
            float xv = hc[r2 * 260 + fc * 64 + fo];
            float4 wv = *(float4*)&ws[fo * 68 + g2 * 4];
            acc[0] += xv * wv.x; acc[1] += xv * wv.y;
            acc[2] += xv * wv.z; acc[3] += xv * wv.w;
        }
    }

    // s,t quads from full-precision acc
    float sp = 0.f, tp = 0.f;
#pragma unroll
    for (int u = 0; u < 4; u++) {
        sp += acc[u] * a_out[g2 * 4 + u];
        tp += acc[u] * a_out[64 + g2 * 4 + u];
    }
#pragma unroll
    for (int mm = 8; mm; mm >>= 1) {
        sp += __shfl_xor_sync(0xffffffffu, sp, mm);
        tp += __shfl_xor_sync(0xffffffffu, tp, mm);
    }
    if (g2 == 0) {
        g_sq[4 * 4096 + i0 + r2] = make_float4(sp, __expf(sp), __expf(ALPHA * sp), 0.f);
        g_tq[4 * 4096 + i0 + r2] = make_float4(tp, __expf(tp), __expf(ALPHA * tp), 0.f);
    }

    *(float4*)(g_WhO + (size_t)(i0 + r2) * 64 + g2 * 4) =
        make_float4(tf32r(acc[0]), tf32r(acc[1]), tf32r(acc[2]), tf32r(acc[3]));
}

// ---------------- kG: combine partials + final linear + elu ----------------
__global__ __launch_bounds__(256) void kG(const float* __restrict__ outlin_w,
                                          const float* __restrict__ outlin_b,
                                          float* __restrict__ out) {
    __shared__ float vi[32 * 68];
    __shared__ float wt[64 * 68];
    const int tid = threadIdx.x;
    const int i0 = blockIdx.x * 32;

#pragma unroll
    for (int u = 0; u < 2; u++) {
        int f4 = tid + 256 * u;
        int r = f4 >> 4, kq = (f4 & 15) * 4;
        int row = i0 + r;
        float4 xa = *(const float4*)&g_xres[(size_t)row * 64 + kq];
        float4 n = *(const float4*)&g_part[(size_t)row * 64 + kq];
        float4 n1 = *(const float4*)&g_part[((size_t)4096 + row) * 64 + kq];
        float4 n2 = *(const float4*)&g_part[((size_t)2 * 4096 + row) * 64 + kq];
        float4 n3 = *(const float4*)&g_part[((size_t)3 * 4096 + row) * 64 + kq];
        n.x += n1.x + n2.x + n3.x;
        n.y += n1.y + n2.y + n3.y;
        n.z += n1.z + n2.z + n3.z;
        n.w += n1.w + n2.w + n3.w;
        float ds = g_denp[row] + g_denp[4096 + row] + g_denp[2 * 4096 + row] +
                   g_denp[3 * 4096 + row];
        float di = 1.f / ds;
        xa.x += elu1(n.x * di);
        xa.y += elu1(n.y * di);
        xa.z += elu1(n.z * di);
        xa.w += elu1(n.w * di);
        *(float4*)&vi[r * 68 + kq] = xa;
    }
#pragma unroll
    for (int u = 0; u < 16; u++) {
        int idx = tid + 256 * u;
        int k2 = idx >> 6, k = idx & 63;
        wt[k * 68 + k2] = outlin_w[k2 * 64 + k];
    }
    __syncthreads();

    const int r = tid >> 3, g = tid & 7;
    float acc[8];
#pragma unroll
    for (int u = 0; u < 8; u++) acc[u] = 0.f;
#pragma unroll 8
    for (int k = 0; k < 64; k++) {
        float xv = vi[r * 68 + k];
        float4 w0 = *(float4*)&wt[k * 68 + g * 4];
        float4 w1 = *(float4*)&wt[k * 68 + 32 + g * 4];
        acc[0] += xv * w0.x; acc[1] += xv * w0.y;
        acc[2] += xv * w0.z; acc[3] += xv * w0.w;
        acc[4] += xv * w1.x; acc[5] += xv * w1.y;
        acc[6] += xv * w1.z; acc[7] += xv * w1.w;
    }
    float* dst = out + (size_t)(i0 + r) * 64;
    *(float4*)(dst + g * 4) = make_float4(
        elu1(acc[0] + outlin_b[g * 4 + 0]), elu1(acc[1] + outlin_b[g * 4 + 1]),
        elu1(acc[2] + outlin_b[g * 4 + 2]), elu1(acc[3] + outlin_b[g * 4 + 3]));
    *(float4*)(dst + 32 + g * 4) = make_float4(
        elu1(acc[4] + outlin_b[32 + g * 4 + 0]), elu1(acc[5] + outlin_b[32 + g * 4 + 1]),
        elu1(acc[6] + outlin_b[32 + g * 4 + 2]), elu1(acc[7] + outlin_b[32 + g * 4 + 3]));
}

// ---------------- launch ----------------
extern "C" void kernel_launch(void* const* d_in, const int* in_sizes, int n_in,
                              void* d_out, int out_size) {
    const float* x        = (const float*)d_in[0];
    const int*   adj      = (const int*)d_in[1];
    const float* w_heads  = (const float*)d_in[2];
    const float* a_heads  = (const float*)d_in[3];
    const float* w_out    = (const float*)d_in[4];
    const float* a_out    = (const float*)d_in[5];
    const float* lin_w    = (const float*)d_in[6];
    const float* lin_b    = (const float*)d_in[7];
    const float* outlin_w = (const float*)d_in[8];
    const float* outlin_b = (const float*)d_in[9];
    float* out = (float*)d_out;

    kP<<<4096, 256>>>(adj);
    kA<<<128, 256>>>(x, w_heads, lin_w, lin_b, a_heads);
    kC<<<dim3(32, 4), 256>>>(0);   // 4 heads -> g_hcat
    kE<<<256, 256>>>(w_out, a_out);
    kC<<<dim3(32, 4), 256>>>(1);   // out layer, 4 j-slices -> partials
    kG<<<128, 256>>>(outlin_w, outlin_b, out);
}

// round 11
// speedup vs baseline: 3.7607x; 1.4974x over previous
#include <cuda_runtime.h>
#include <cuda_bf16.h>
#include <cstdint>

#define ALPHA 0.2f

// ---------------- persistent scratch ----------------
// WhT bf16 [layer 0..4][64 cols][4096 nodes], stored as uint4 for alignment
__device__ uint4    g_WhT4[5 * 64 * 4096 / 8];
__device__ float2   g_sq2[5 * 4096];          // (e^s, e^{0.2s})
__device__ float2   g_tq2[5 * 4096];          // (e^t, e^{0.2t})
__device__ unsigned g_adjbits[4096 * 128];    // bit-packed adjacency
__device__ float    g_xres[4096 * 64];
__device__ float    g_part[8 * 4096 * 64];    // partial numerators (8 slots)
__device__ float    g_denp[8 * 4096];         // partial denominators

// ---------------- helpers ----------------
__device__ __forceinline__ float elu1(float v) {
    return v > 0.f ? v : (__expf(v) - 1.f);
}
__device__ __forceinline__ void cp16(void* smem_dst, const void* gsrc) {
    unsigned d = (unsigned)__cvta_generic_to_shared(smem_dst);
    asm volatile("cp.async.cg.shared.global [%0], [%1], 16;" :: "r"(d), "l"(gsrc));
}
__device__ __forceinline__ unsigned pkbf(float lo, float hi) {
    unsigned d;
    asm("cvt.rn.bf16x2.f32 %0, %1, %2;" : "=r"(d) : "f"(hi), "f"(lo));
    return d;
}
__device__ __forceinline__ void mma16(float* d, const unsigned* a, unsigned b0, unsigned b1) {
    asm volatile(
        "mma.sync.aligned.m16n8k16.row.col.f32.bf16.bf16.f32 "
        "{%0,%1,%2,%3},{%4,%5,%6,%7},{%8,%9},{%0,%1,%2,%3};"
        : "+f"(d[0]), "+f"(d[1]), "+f"(d[2]), "+f"(d[3])
        : "r"(a[0]), "r"(a[1]), "r"(a[2]), "r"(a[3]), "r"(b0), "r"(b1));
}
#define ONESBF 0x3F803F80u

// ---------------- kP: bit-pack adjacency ----------------
__global__ __launch_bounds__(256) void kP(const int* __restrict__ adj) {
    const int row = blockIdx.x;
    const int w = threadIdx.x >> 5, lane = threadIdx.x & 31;
    const int* base = adj + (size_t)row * 4096;
#pragma unroll
    for (int it = 0; it < 16; it++) {
        int col = (w * 16 + it) * 32 + lane;
        unsigned m = __ballot_sync(0xffffffffu, base[col] > 0);
        if (lane == 0) g_adjbits[row * 128 + w * 16 + it] = m;
    }
}

// ---------------- kA: per-head Wh^T (bf16) + s,t quads + x_residual ----------------
__global__ __launch_bounds__(256) void kA(const float* __restrict__ x,
                                          const float* __restrict__ w_heads,
                                          const float* __restrict__ lin_w,
                                          const float* __restrict__ lin_b,
                                          const float* __restrict__ a_heads) {
    __shared__ float xs[32 * 132];
    __shared__ float ws[64 * 68];
    __shared__ float tr[64 * 36];
    const int tid = threadIdx.x;
    const int i0 = blockIdx.x * 32;

#pragma unroll
    for (int u = 0; u < 16; u++) {
        int idx = tid + 256 * u;
        int r = idx >> 7, f = idx & 127;
        xs[r * 132 + f] = x[(i0 + r) * 128 + f];
    }

    const int r = tid >> 3, g = tid & 7;

    for (int cc = 0; cc < 5; cc++) {
        float acc[8];
#pragma unroll
        for (int u = 0; u < 8; u++) acc[u] = 0.f;

        for (int fh = 0; fh < 2; fh++) {
            __syncthreads();
            if (cc < 4) {
#pragma unroll
                for (int u = 0; u < 4; u++) {
                    int f4 = tid + 256 * u;
                    int jj = f4 >> 4, kq = (f4 & 15) * 4;
                    *(float4*)&ws[jj * 68 + kq] =
                        *(const float4*)&w_heads[(cc * 128 + fh * 64 + jj) * 64 + kq];
                }
            } else {
#pragma unroll
                for (int u = 0; u < 16; u++) {
                    int idx = tid + 256 * u;
                    int k = idx >> 6, fo = idx & 63;
                    ws[fo * 68 + k] = lin_w[k * 128 + fh * 64 + fo];
                }
            }
            __syncthreads();
#pragma unroll 8
            for (int fo = 0; fo < 64; fo++) {
                float xv = xs[r * 132 + fh * 64 + fo];
                float4 w0 = *(float4*)&ws[fo * 68 + g * 4];
                float4 w1 = *(float4*)&ws[fo * 68 + 32 + g * 4];
                acc[0] += xv * w0.x; acc[1] += xv * w0.y;
                acc[2] += xv * w0.z; acc[3] += xv * w0.w;
                acc[4] += xv * w1.x; acc[5] += xv * w1.y;
                acc[6] += xv * w1.z; acc[7] += xv * w1.w;
            }
        }

        if (cc < 4) {
            // s,t quads from full-precision acc
            const float* av = a_heads + cc * 128;
            float sp = 0.f, tp = 0.f;
#pragma unroll
            for (int u = 0; u < 4; u++) {
                int c0 = g * 4 + u, c1 = 32 + g * 4 + u;
                sp += acc[u] * av[c0] + acc[4 + u] * av[c1];
                tp += acc[u] * av[64 + c0] + acc[4 + u] * av[64 + c1];
            }
            sp += __shfl_xor_sync(0xffffffffu, sp, 1);
            sp += __shfl_xor_sync(0xffffffffu, sp, 2);
            sp += __shfl_xor_sync(0xffffffffu, sp, 4);
            tp += __shfl_xor_sync(0xffffffffu, tp, 1);
            tp += __shfl_xor_sync(0xffffffffu, tp, 2);
            tp += __shfl_xor_sync(0xffffffffu, tp, 4);
            if (g == 0) {
                g_sq2[cc * 4096 + i0 + r] = make_float2(__expf(sp), __expf(ALPHA * sp));
                g_tq2[cc * 4096 + i0 + r] = make_float2(__expf(tp), __expf(ALPHA * tp));
            }
            // transpose -> bf16 WhT
#pragma unroll
            for (int u = 0; u < 4; u++) {
                tr[(g * 4 + u) * 36 + r] = acc[u];
                tr[(32 + g * 4 + u) * 36 + r] = acc[4 + u];
            }
            __syncthreads();
            {
                int c = tid >> 2, seg = tid & 3;
                float v[8];
#pragma unroll
                for (int q = 0; q < 8; q++) v[q] = tr[c * 36 + seg * 8 + q];
                uint4 pk;
                pk.x = pkbf(v[0], v[1]);
                pk.y = pkbf(v[2], v[3]);
                pk.z = pkbf(v[4], v[5]);
                pk.w = pkbf(v[6], v[7]);
                g_WhT4[(((size_t)(cc * 64 + c)) * 4096 + i0 + seg * 8) >> 3] = pk;
            }
            __syncthreads();
        } else {
            float* dst = g_xres + (size_t)(i0 + r) * 64;
            *(float4*)(dst + g * 4) =
                make_float4(acc[0] + lin_b[g * 4 + 0], acc[1] + lin_b[g * 4 + 1],
                            acc[2] + lin_b[g * 4 + 2], acc[3] + lin_b[g * 4 + 3]);
            *(float4*)(dst + 32 + g * 4) =
                make_float4(acc[4] + lin_b[32 + g * 4 + 0], acc[5] + lin_b[32 + g * 4 + 1],
                            acc[6] + lin_b[32 + g * 4 + 2], acc[7] + lin_b[32 + g * 4 + 3]);
        }
    }
}

// ---------------- kC: fused attention, bf16 m16n8k16, 256 rows/block, j-split ----------------
// mode 0: y = head*2 + jslice(2048-wide), T=32   mode 1: y = jslice(512-wide), T=8
// Writes partial numerators -> g_part[slot=y], partial denominators -> g_denp[slot=y].
__global__ __launch_bounds__(256) void kC(int mode) {
    __shared__ __align__(16) __nv_bfloat16 whs[2][64][72];  // B tile, [col][j], stride 72
    __shared__ __align__(16) float2 tst[2][64];             // t quads

    const int tid = threadIdx.x;
    const int w = tid >> 5, lane = tid & 31;
    const int k = lane & 3, m = lane >> 2;
    const int i0 = blockIdx.x * 256;
    const int y = blockIdx.y;

    int lay, jlo, T;
    if (mode == 0) { lay = y >> 1; jlo = (y & 1) * 2048; T = 32; }
    else           { lay = 4;      jlo = y * 512;        T = 8;  }

    const __nv_bfloat16* WhB = (const __nv_bfloat16*)g_WhT4 + (size_t)lay * 64 * 4096;
    const float2* tq = g_tq2 + lay * 4096;
    const float2* sq = g_sq2 + lay * 4096;

    const int r0 = i0 + 32 * w + m;
    const float2 e0 = sq[r0], e1 = sq[r0 + 8], e2 = sq[r0 + 16], e3 = sq[r0 + 24];
    const unsigned* am0 = g_adjbits + (size_t)r0 * 128 + (jlo >> 5);
    const unsigned* am1 = am0 + 8 * 128;
    const unsigned* am2 = am0 + 16 * 128;
    const unsigned* am3 = am0 + 24 * 128;

    float accA[9][4], accB[9][4];
#pragma unroll
    for (int n = 0; n < 9; n++)
#pragma unroll
        for (int u = 0; u < 4; u++) { accA[n][u] = 0.f; accB[n][u] = 0.f; }

    // ---- preload tile 0 ----
#pragma unroll
    for (int u = 0; u < 2; u++) {
        int idx = tid + 256 * u;
        int c = idx >> 3, ch = idx & 7;
        cp16(&whs[0][c][ch * 8], WhB + (size_t)c * 4096 + jlo + ch * 8);
    }
    if (tid < 32) cp16(&tst[0][tid * 2], tq + jlo + tid * 2);
    asm volatile("cp.async.commit_group;");
    uint2 M0 = *(const uint2*)am0;
    uint2 M1 = *(const uint2*)am1;
    uint2 M2 = *(const uint2*)am2;
    uint2 M3 = *(const uint2*)am3;
    asm volatile("cp.async.wait_group 0;" ::: "memory");
    __syncthreads();

    for (int t = 0; t < T; t++) {
        const int b = t & 1, nb = b ^ 1;

        // prefetch tile t+1
        uint2 N0, N1, N2, N3;
        if (t + 1 < T) {
            const int j0n = jlo + (t + 1) * 64;
#pragma unroll
            for (int u = 0; u < 2; u++) {
                int idx = tid + 256 * u;
                int c = idx >> 3, ch = idx & 7;
                cp16(&whs[nb][c][ch * 8], WhB + (size_t)c * 4096 + j0n + ch * 8);
            }
            if (tid < 32) cp16(&tst[nb][tid * 2], tq + j0n + tid * 2);
            asm volatile("cp.async.commit_group;");
            N0 = *(const uint2*)(am0 + 2 * (t + 1));
            N1 = *(const uint2*)(am1 + 2 * (t + 1));
            N2 = *(const uint2*)(am2 + 2 * (t + 1));
            N3 = *(const uint2*)(am3 + 2 * (t + 1));
        }

        // ---- phase 1 + mma, per 16-wide k-step ----
#pragma unroll
        for (int s = 0; s < 4; s++) {
            const float4 tA = *(const float4*)&tst[b][16 * s + 2 * k];      // cols c0, c0+1
            const float4 tB = *(const float4*)&tst[b][16 * s + 2 * k + 8];  // cols c0+8, c0+9
            const int sh = (s & 1) * 16 + 2 * k;
            const unsigned h0 = ((s >= 2) ? M0.y : M0.x) >> sh;
            const unsigned h1 = ((s >= 2) ? M1.y : M1.x) >> sh;
            const unsigned h2 = ((s >= 2) ? M2.y : M2.x) >> sh;
            const unsigned h3 = ((s >= 2) ? M3.y : M3.x) >> sh;

            unsigned afrA[4], afrB[4];
            {
                float p0 = (h0 & 1u) ? fmaxf(e0.x * tA.x, e0.y * tA.y) : 0.f;
                float p1 = ((h0 >> 1) & 1u) ? fmaxf(e0.x * tA.z, e0.y * tA.w) : 0.f;
                float p8 = ((h0 >> 8) & 1u) ? fmaxf(e0.x * tB.x, e0.y * tB.y) : 0.f;
                float p9 = ((h0 >> 9) & 1u) ? fmaxf(e0.x * tB.z, e0.y * tB.w) : 0.f;
                afrA[0] = pkbf(p0, p1); afrA[2] = pkbf(p8, p9);
            }
            {
                float p0 = (h1 & 1u) ? fmaxf(e1.x * tA.x, e1.y * tA.y) : 0.f;
                float p1 = ((h1 >> 1) & 1u) ? fmaxf(e1.x * tA.z, e1.y * tA.w) : 0.f;
                float p8 = ((h1 >> 8) & 1u) ? fmaxf(e1.x * tB.x, e1.y * tB.y) : 0.f;
                float p9 = ((h1 >> 9) & 1u) ? fmaxf(e1.x * tB.z, e1.y * tB.w) : 0.f;
                afrA[1] = pkbf(p0, p1); afrA[3] = pkbf(p8, p9);
            }
            {
                float p0 = (h2 & 1u) ? fmaxf(e2.x * tA.x, e2.y * tA.y) : 0.f;
                float p1 = ((h2 >> 1) & 1u) ? fmaxf(e2.x * tA.z, e2.y * tA.w) : 0.f;
                float p8 = ((h2 >> 8) & 1u) ? fmaxf(e2.x * tB.x, e2.y * tB.y) : 0.f;
                float p9 = ((h2 >> 9) & 1u) ? fmaxf(e2.x * tB.z, e2.y * tB.w) : 0.f;
                afrB[0] = pkbf(p0, p1); afrB[2] = pkbf(p8, p9);
            }
            {
                float p0 = (h3 & 1u) ? fmaxf(e3.x * tA.x, e3.y * tA.y) : 0.f;
                float p1 = ((h3 >> 1) & 1u) ? fmaxf(e3.x * tA.z, e3.y * tA.w) : 0.f;
                float p8 = ((h3 >> 8) & 1u) ? fmaxf(e3.x * tB.x, e3.y * tB.y) : 0.f;
                float p9 = ((h3 >> 9) & 1u) ? fmaxf(e3.x * tB.z, e3.y * tB.w) : 0.f;
                afrB[1] = pkbf(p0, p1); afrB[3] = pkbf(p8, p9);
            }

#pragma unroll
            for (int n = 0; n < 8; n++) {
                const __nv_bfloat16* bp = &whs[b][8 * n + m][16 * s + 2 * k];
                unsigned b0 = *(const unsigned*)bp;
                unsigned b1 = *(const unsigned*)(bp + 8);
                mma16(accA[n], afrA, b0, b1);
                mma16(accB[n], afrB, b0, b1);
            }
            // denominator column: B = ones
            mma16(accA[8], afrA, ONESBF, ONESBF);
            mma16(accB[8], afrB, ONESBF, ONESBF);
        }

        if (t + 1 < T) {
            asm volatile("cp.async.wait_group 0;" ::: "memory");
            M0 = N0; M1 = N1; M2 = N2; M3 = N3;
        }
        __syncthreads();
    }

    // ---- epilogue: write partials ----
    const int slot = y;
    float* p0 = g_part + ((size_t)slot * 4096 + r0) * 64 + 2 * k;
    float* p1 = p0 + 8 * 64;
    float* p2 = p0 + 16 * 64;
    float* p3 = p0 + 24 * 64;
#pragma unroll
    for (int n = 0; n < 8; n++) {
        *(float2*)(p0 + 8 * n) = make_float2(accA[n][0], accA[n][1]);
        *(float2*)(p1 + 8 * n) = make_float2(accA[n][2], accA[n][3]);
        *(float2*)(p2 + 8 * n) = make_float2(accB[n][0], accB[n][1]);
        *(float2*)(p3 + 8 * n) = make_float2(accB[n][2], accB[n][3]);
    }
    if (k == 0) {
        g_denp[slot * 4096 + r0] = accA[8][0];
        g_denp[slot * 4096 + r0 + 8] = accA[8][2];
        g_denp[slot * 4096 + r0 + 16] = accB[8][0];
        g_denp[slot * 4096 + r0 + 24] = accB[8][2];
    }
}

// ---------------- kE: combine heads + out-layer Wh^T (bf16) + quads ----------------
extern __shared__ float smE[];
__global__ __launch_bounds__(256) void kE(const float* __restrict__ w_out,
                                          const float* __restrict__ a_out) {
    float* ws = smE;               // 256*68
    float* hc = smE + 256 * 68;    // 32*260 (tr overlays later)
    __shared__ float dhs[32 * 4];
    const int tid = threadIdx.x;
    const int i0 = blockIdx.x * 32;

    // load full w_out
#pragma unroll
    for (int u = 0; u < 16; u++) {
        int idx = tid + 256 * u;
        int kk = idx >> 4, q = (idx & 15) * 4;
        *(float4*)&ws[kk * 68 + q] = *(const float4*)&w_out[kk * 64 + q];
    }
    if (tid < 128) {
        int r = tid >> 2, h = tid & 3, row = i0 + r;
        dhs[r * 4 + h] =
            1.f / (g_denp[(2 * h) * 4096 + row] + g_denp[(2 * h + 1) * 4096 + row]);
    }
    __syncthreads();

    // combine head partials -> hc (= elu(num/den)), layout [row][head*64+c]
#pragma unroll
    for (int u = 0; u < 8; u++) {
        int idx = tid + 256 * u;
        int r = idx >> 6, cg = idx & 63;
        int h = cg >> 4, cc = (cg & 15) * 4;
        int row = i0 + r;
        const float* pa = g_part + ((size_t)(2 * h) * 4096 + row) * 64 + cc;
        const float* pb = pa + 4096 * 64;
        float4 va = *(const float4*)pa;
        float4 vb = *(const float4*)pb;
        float di = dhs[r * 4 + h];
        float* d = &hc[r * 260 + h * 64 + cc];
        d[0] = elu1((va.x + vb.x) * di);
        d[1] = elu1((va.y + vb.y) * di);
        d[2] = elu1((va.z + vb.z) * di);
        d[3] = elu1((va.w + vb.w) * di);
    }
    __syncthreads();

    const int r = tid >> 3, g = tid & 7;
    float acc[8];
#pragma unroll
    for (int u = 0; u < 8; u++) acc[u] = 0.f;
#pragma unroll 8
    for (int kk = 0; kk < 256; kk++) {
        float xv = hc[r * 260 + kk];
        float4 w0 = *(float4*)&ws[kk * 68 + g * 4];
        float4 w1 = *(float4*)&ws[kk * 68 + 32 + g * 4];
        acc[0] += xv * w0.x; acc[1] += xv * w0.y;
        acc[2] += xv * w0.z; acc[3] += xv * w0.w;
        acc[4] += xv * w1.x; acc[5] += xv * w1.y;
        acc[6] += xv * w1.z; acc[7] += xv * w1.w;
    }

    // layer-4 s,t quads
    float sp = 0.f, tp = 0.f;
#pragma unroll
    for (int u = 0; u < 4; u++) {
        int c0 = g * 4 + u, c1 = 32 + g * 4 + u;
        sp += acc[u] * a_out[c0] + acc[4 + u] * a_out[c1];
        tp += acc[u] * a_out[64 + c0] + acc[4 + u] * a_out[64 + c1];
    }
    sp += __shfl_xor_sync(0xffffffffu, sp, 1);
    sp += __shfl_xor_sync(0xffffffffu, sp, 2);
    sp += __shfl_xor_sync(0xffffffffu, sp, 4);
    tp += __shfl_xor_sync(0xffffffffu, tp, 1);
    tp += __shfl_xor_sync(0xffffffffu, tp, 2);
    tp += __shfl_xor_sync(0xffffffffu, tp, 4);
    if (g == 0) {
        g_sq2[4 * 4096 + i0 + r] = make_float2(__expf(sp), __expf(ALPHA * sp));
        g_tq2[4 * 4096 + i0 + r] = make_float2(__expf(tp), __expf(ALPHA * tp));
    }

    // transpose -> bf16 out-layer WhT (tr overlays hc)
    __syncthreads();
    float* tr = hc;
#pragma unroll
    for (int u = 0; u < 4; u++) {
        tr[(g * 4 + u) * 36 + r] = acc[u];
        tr[(32 + g * 4 + u) * 36 + r] = acc[4 + u];
    }
    __syncthreads();
    {
        int c = tid >> 2, seg = tid & 3;
        float v[8];
#pragma unroll
        for (int q = 0; q < 8; q++) v[q] = tr[c * 36 + seg * 8 + q];
        uint4 pk;
        pk.x = pkbf(v[0], v[1]);
        pk.y = pkbf(v[2], v[3]);
        pk.z = pkbf(v[4], v[5]);
        pk.w = pkbf(v[6], v[7]);
        g_WhT4[(((size_t)(4 * 64 + c)) * 4096 + i0 + seg * 8) >> 3] = pk;
    }
}

// ---------------- kG: combine out-layer partials + residual + final linear + elu ----------------
__global__ __launch_bounds__(256) void kG(const float* __restrict__ outlin_w,
                                          const float* __restrict__ outlin_b,
                                          float* __restrict__ out) {
    __shared__ float vi[32 * 68];
    __shared__ float wt[64 * 68];
    __shared__ float dinv[32];
    const int tid = threadIdx.x;
    const int i0 = blockIdx.x * 32;

    if (tid < 32) {
        int row = i0 + tid;
        float ds = 0.f;
#pragma unroll
        for (int s = 0; s < 8; s++) ds += g_denp[s * 4096 + row];
        dinv[tid] = 1.f / ds;
    }
#pragma unroll
    for (int u = 0; u < 16; u++) {
        int idx = tid + 256 * u;
        int k2 = idx >> 6, k = idx & 63;
        wt[k * 68 + k2] = outlin_w[k2 * 64 + k];
    }
    __syncthreads();

#pragma unroll
    for (int u = 0; u < 2; u++) {
        int idx = tid + 256 * u;
        int r = idx >> 4, kq = (idx & 15) * 4;
        int row = i0 + r;
        float4 n = make_float4(0.f, 0.f, 0.f, 0.f);
#pragma unroll
        for (int s = 0; s < 8; s++) {
            float4 v = *(const float4*)&g_part[((size_t)s * 4096 + row) * 64 + kq];
            n.x += v.x; n.y += v.y; n.z += v.z; n.w += v.w;
        }
        float4 xa = *(const float4*)&g_xres[(size_t)row * 64 + kq];
        float di = dinv[r];
        xa.x += elu1(n.x * di);
        xa.y += elu1(n.y * di);
        xa.z += elu1(n.z * di);
        xa.w += elu1(n.w * di);
        *(float4*)&vi[r * 68 + kq] = xa;
    }
    __syncthreads();

    const int r = tid >> 3, g = tid & 7;
    float acc[8];
#pragma unroll
    for (int u = 0; u < 8; u++) acc[u] = 0.f;
#pragma unroll 8
    for (int k = 0; k < 64; k++) {
        float xv = vi[r * 68 + k];
        float4 w0 = *(float4*)&wt[k * 68 + g * 4];
        float4 w1 = *(float4*)&wt[k * 68 + 32 + g * 4];
        acc[0] += xv * w0.x; acc[1] += xv * w0.y;
        acc[2] += xv * w0.z; acc[3] += xv * w0.w;
        acc[4] += xv * w1.x; acc[5] += xv * w1.y;
        acc[6] += xv * w1.z; acc[7] += xv * w1.w;
    }
    float* dst = out + (size_t)(i0 + r) * 64;
    *(float4*)(dst + g * 4) = make_float4(
        elu1(acc[0] + outlin_b[g * 4 + 0]), elu1(acc[1] + outlin_b[g * 4 + 1]),
        elu1(acc[2] + outlin_b[g * 4 + 2]), elu1(acc[3] + outlin_b[g * 4 + 3]));
    *(float4*)(dst + 32 + g * 4) = make_float4(
        elu1(acc[4] + outlin_b[32 + g * 4 + 0]), elu1(acc[5] + outlin_b[32 + g * 4 + 1]),
        elu1(acc[6] + outlin_b[32 + g * 4 + 2]), elu1(acc[7] + outlin_b[32 + g * 4 + 3]));
}

// ---------------- launch ----------------
extern "C" void kernel_launch(void* const* d_in, const int* in_sizes, int n_in,
                              void* d_out, int out_size) {
    const float* x        = (const float*)d_in[0];
    const int*   adj      = (const int*)d_in[1];
    const float* w_heads  = (const float*)d_in[2];
    const float* a_heads  = (const float*)d_in[3];
    const float* w_out    = (const float*)d_in[4];
    const float* a_out    = (const float*)d_in[5];
    const float* lin_w    = (const float*)d_in[6];
    const float* lin_b    = (const float*)d_in[7];
    const float* outlin_w = (const float*)d_in[8];
    const float* outlin_b = (const float*)d_in[9];
    float* out = (float*)d_out;

    const int SMEM_E = (256 * 68 + 32 * 260) * 4;  // 102,912 B
    static int inited = 0;
    if (!inited) {
        cudaFuncSetAttribute(kE, cudaFuncAttributeMaxDynamicSharedMemorySize, SMEM_E);
        inited = 1;
    }

    kP<<<4096, 256>>>(adj);
    kA<<<128, 256>>>(x, w_heads, lin_w, lin_b, a_heads);
    kC<<<dim3(16, 8), 256>>>(0);            // 4 heads x 2 j-slices -> partials
    kE<<<128, 256, SMEM_E>>>(w_out, a_out); // combine heads + out-layer WhT + quads
    kC<<<dim3(16, 8), 256>>>(1);            // out layer, 8 j-slices -> partials
    kG<<<128, 256>>>(outlin_w, outlin_b, out);
}

// round 14
// speedup vs baseline: 4.1592x; 1.1060x over previous
#include <cuda_runtime.h>
#include <cuda_bf16.h>
#include <cstdint>

#define ALPHA 0.2f

// ---------------- persistent scratch ----------------
__device__ uint4    g_WhT4[5 * 64 * 4096 / 8];   // WhT bf16 [layer][64 cols][4096 nodes]
__device__ float2   g_sq2[5 * 4096];             // (e^s, e^{0.2s})
__device__ float2   g_tq2[5 * 4096];             // (e^t, e^{0.2t})
__device__ unsigned g_adjbits[4096 * 128];       // bit-packed adjacency
__device__ float    g_xres[4096 * 64];
__device__ float    g_part[8 * 4096 * 64];       // partial numerators (8 slots)
__device__ float    g_denp[8 * 4096];            // partial denominators

// ---------------- helpers ----------------
__device__ __forceinline__ float elu1(float v) {
    return v > 0.f ? v : (__expf(v) - 1.f);
}
__device__ __forceinline__ void cp16(void* smem_dst, const void* gsrc) {
    unsigned d = (unsigned)__cvta_generic_to_shared(smem_dst);
    asm volatile("cp.async.cg.shared.global [%0], [%1], 16;" :: "r"(d), "l"(gsrc));
}
__device__ __forceinline__ unsigned pkbf(float lo, float hi) {
    unsigned d;
    asm("cvt.rn.bf16x2.f32 %0, %1, %2;" : "=r"(d) : "f"(hi), "f"(lo));
    return d;
}
__device__ __forceinline__ void mma16(float* d, const unsigned* a, unsigned b0, unsigned b1) {
    asm volatile(
        "mma.sync.aligned.m16n8k16.row.col.f32.bf16.bf16.f32 "
        "{%0,%1,%2,%3},{%4,%5,%6,%7},{%8,%9},{%0,%1,%2,%3};"
        : "+f"(d[0]), "+f"(d[1]), "+f"(d[2]), "+f"(d[3])
        : "r"(a[0]), "r"(a[1]), "r"(a[2]), "r"(a[3]), "r"(b0), "r"(b1));
}
#define ONESBF 0x3F803F80u

// ---------------- kP: bit-pack adjacency ----------------
__global__ __launch_bounds__(256) void kP(const int* __restrict__ adj) {
    const int row = blockIdx.x;
    const int w = threadIdx.x >> 5, lane = threadIdx.x & 31;
    const int* base = adj + (size_t)row * 4096;
#pragma unroll
    for (int it = 0; it < 16; it++) {
        int col = (w * 16 + it) * 32 + lane;
        unsigned m = __ballot_sync(0xffffffffu, base[col] > 0);
        if (lane == 0) g_adjbits[row * 128 + w * 16 + it] = m;
    }
}

// ---------------- kA: Wh^T (bf16) + s,t quads + x_residual; blockIdx.y = weight set ----------------
__global__ __launch_bounds__(256) void kA(const float* __restrict__ x,
                                          const float* __restrict__ w_heads,
                                          const float* __restrict__ lin_w,
                                          const float* __restrict__ lin_b,
                                          const float* __restrict__ a_heads) {
    __shared__ float xs[32 * 132];
    __shared__ float ws[64 * 68];
    __shared__ float tr[64 * 36];
    const int tid = threadIdx.x;
    const int i0 = blockIdx.x * 32;
    const int cc = blockIdx.y;

#pragma unroll
    for (int u = 0; u < 16; u++) {
        int idx = tid + 256 * u;
        int r = idx >> 7, f = idx & 127;
        xs[r * 132 + f] = x[(i0 + r) * 128 + f];
    }

    const int r = tid >> 3, g = tid & 7;
    float acc[8];
#pragma unroll
    for (int u = 0; u < 8; u++) acc[u] = 0.f;

    for (int fh = 0; fh < 2; fh++) {
        __syncthreads();
        if (cc < 4) {
#pragma unroll
            for (int u = 0; u < 4; u++) {
                int f4 = tid + 256 * u;
                int jj = f4 >> 4, kq = (f4 & 15) * 4;
                *(float4*)&ws[jj * 68 + kq] =
                    *(const float4*)&w_heads[(cc * 128 + fh * 64 + jj) * 64 + kq];
            }
        } else {
#pragma unroll
            for (int u = 0; u < 16; u++) {
                int idx = tid + 256 * u;
                int k = idx >> 6, fo = idx & 63;
                ws[fo * 68 + k] = lin_w[k * 128 + fh * 64 + fo];
            }
        }
        __syncthreads();
#pragma unroll 8
        for (int fo = 0; fo < 64; fo++) {
            float xv = xs[r * 132 + fh * 64 + fo];
            float4 w0 = *(float4*)&ws[fo * 68 + g * 4];
            float4 w1 = *(float4*)&ws[fo * 68 + 32 + g * 4];
            acc[0] += xv * w0.x; acc[1] += xv * w0.y;
            acc[2] += xv * w0.z; acc[3] += xv * w0.w;
            acc[4] += xv * w1.x; acc[5] += xv * w1.y;
            acc[6] += xv * w1.z; acc[7] += xv * w1.w;
        }
    }

    if (cc < 4) {
        const float* av = a_heads + cc * 128;
        float sp = 0.f, tp = 0.f;
#pragma unroll
        for (int u = 0; u < 4; u++) {
            int c0 = g * 4 + u, c1 = 32 + g * 4 + u;
            sp += acc[u] * __ldg(av + c0) + acc[4 + u] * __ldg(av + c1);
            tp += acc[u] * __ldg(av + 64 + c0) + acc[4 + u] * __ldg(av + 64 + c1);
        }
        sp += __shfl_xor_sync(0xffffffffu, sp, 1);
        sp += __shfl_xor_sync(0xffffffffu, sp, 2);
        sp += __shfl_xor_sync(0xffffffffu, sp, 4);
        tp += __shfl_xor_sync(0xffffffffu, tp, 1);
        tp += __shfl_xor_sync(0xffffffffu, tp, 2);
        tp += __shfl_xor_sync(0xffffffffu, tp, 4);
        if (g == 0) {
            g_sq2[cc * 4096 + i0 + r] = make_float2(__expf(sp), __expf(ALPHA * sp));
            g_tq2[cc * 4096 + i0 + r] = make_float2(__expf(tp), __expf(ALPHA * tp));
        }
        // transpose -> bf16 WhT
#pragma unroll
        for (int u = 0; u < 4; u++) {
            tr[(g * 4 + u) * 36 + r] = acc[u];
            tr[(32 + g * 4 + u) * 36 + r] = acc[4 + u];
        }
        __syncthreads();
        {
            int c = tid >> 2, seg = tid & 3;
            float v[8];
#pragma unroll
            for (int q = 0; q < 8; q++) v[q] = tr[c * 36 + seg * 8 + q];
            uint4 pk;
            pk.x = pkbf(v[0], v[1]);
            pk.y = pkbf(v[2], v[3]);
            pk.z = pkbf(v[4], v[5]);
            pk.w = pkbf(v[6], v[7]);
            g_WhT4[(((size_t)(cc * 64 + c)) * 4096 + i0 + seg * 8) >> 3] = pk;
        }
    } else {
        float* dst = g_xres + (size_t)(i0 + r) * 64;
        *(float4*)(dst + g * 4) =
            make_float4(acc[0] + lin_b[g * 4 + 0], acc[1] + lin_b[g * 4 + 1],
                        acc[2] + lin_b[g * 4 + 2], acc[3] + lin_b[g * 4 + 3]);
        *(float4*)(dst + 32 + g * 4) =
            make_float4(acc[4] + lin_b[32 + g * 4 + 0], acc[5] + lin_b[32 + g * 4 + 1],
                        acc[6] + lin_b[32 + g * 4 + 2], acc[7] + lin_b[32 + g * 4 + 3]);
    }
}

// ---------------- kC: fused attention, bf16 m16n8k16, 256 rows/block, j-split ----------------
__global__ __launch_bounds__(256) void kC(int mode) {
    __shared__ __align__(16) __nv_bfloat16 whs[2][64][72];
    __shared__ __align__(16) float2 tst[2][64];

    const int tid = threadIdx.x;
    const int w = tid >> 5, lane = tid & 31;
    const int k = lane & 3, m = lane >> 2;
    const int i0 = blockIdx.x * 256;
    const int y = blockIdx.y;

    int lay, jlo, T;
    if (mode == 0) { lay = y >> 1; jlo = (y & 1) * 2048; T = 32; }
    else           { lay = 4;      jlo = y * 512;        T = 8;  }

    const __nv_bfloat16* WhB = (const __nv_bfloat16*)g_WhT4 + (size_t)lay * 64 * 4096;
    const float2* tq = g_tq2 + lay * 4096;
    const float2* sq = g_sq2 + lay * 4096;

    const int r0 = i0 + 32 * w + m;
    const float2 e0 = sq[r0], e1 = sq[r0 + 8], e2 = sq[r0 + 16], e3 = sq[r0 + 24];
    const unsigned* am0 = g_adjbits + (size_t)r0 * 128 + (jlo >> 5);
    const unsigned* am1 = am0 + 8 * 128;
    const unsigned* am2 = am0 + 16 * 128;
    const unsigned* am3 = am0 + 24 * 128;

    float accA[9][4], accB[9][4];
#pragma unroll
    for (int n = 0; n < 9; n++)
#pragma unroll
        for (int u = 0; u < 4; u++) { accA[n][u] = 0.f; accB[n][u] = 0.f; }

#pragma unroll
    for (int u = 0; u < 2; u++) {
        int idx = tid + 256 * u;
        int c = idx >> 3, ch = idx & 7;
        cp16(&whs[0][c][ch * 8], WhB + (size_t)c * 4096 + jlo + ch * 8);
    }
    if (tid < 32) cp16(&tst[0][tid * 2], tq + jlo + tid * 2);
    asm volatile("cp.async.commit_group;");
    uint2 M0 = *(const uint2*)am0;
    uint2 M1 = *(const uint2*)am1;
    uint2 M2 = *(const uint2*)am2;
    uint2 M3 = *(const uint2*)am3;
    asm volatile("cp.async.wait_group 0;" ::: "memory");
    __syncthreads();

    for (int t = 0; t < T; t++) {
        const int b = t & 1, nb = b ^ 1;

        uint2 N0, N1, N2, N3;
        if (t + 1 < T) {
            const int j0n = jlo + (t + 1) * 64;
#pragma unroll
            for (int u = 0; u < 2; u++) {
                int idx = tid + 256 * u;
                int c = idx >> 3, ch = idx & 7;
                cp16(&whs[nb][c][ch * 8], WhB + (size_t)c * 4096 + j0n + ch * 8);
            }
            if (tid < 32) cp16(&tst[nb][tid * 2], tq + j0n + tid * 2);
            asm volatile("cp.async.commit_group;");
            N0 = *(const uint2*)(am0 + 2 * (t + 1));
            N1 = *(const uint2*)(am1 + 2 * (t + 1));
            N2 = *(const uint2*)(am2 + 2 * (t + 1));
            N3 = *(const uint2*)(am3 + 2 * (t + 1));
        }

#pragma unroll
        for (int s = 0; s < 4; s++) {
            const float4 tA = *(const float4*)&tst[b][16 * s + 2 * k];
            const float4 tB = *(const float4*)&tst[b][16 * s + 2 * k + 8];
            const int sh = (s & 1) * 16 + 2 * k;
            const unsigned h0 = ((s >= 2) ? M0.y : M0.x) >> sh;
            const unsigned h1 = ((s >= 2) ? M1.y : M1.x) >> sh;
            const unsigned h2 = ((s >= 2) ? M2.y : M2.x) >> sh;
            const unsigned h3 = ((s >= 2) ? M3.y : M3.x) >> sh;

            unsigned afrA[4], afrB[4];
            {
                float p0 = (h0 & 1u) ? fmaxf(e0.x * tA.x, e0.y * tA.y) : 0.f;
                float p1 = ((h0 >> 1) & 1u) ? fmaxf(e0.x * tA.z, e0.y * tA.w) : 0.f;
                float p8 = ((h0 >> 8) & 1u) ? fmaxf(e0.x * tB.x, e0.y * tB.y) : 0.f;
                float p9 = ((h0 >> 9) & 1u) ? fmaxf(e0.x * tB.z, e0.y * tB.w) : 0.f;
                afrA[0] = pkbf(p0, p1); afrA[2] = pkbf(p8, p9);
            }
            {
                float p0 = (h1 & 1u) ? fmaxf(e1.x * tA.x, e1.y * tA.y) : 0.f;
                float p1 = ((h1 >> 1) & 1u) ? fmaxf(e1.x * tA.z, e1.y * tA.w) : 0.f;
                float p8 = ((h1 >> 8) & 1u) ? fmaxf(e1.x * tB.x, e1.y * tB.y) : 0.f;
                float p9 = ((h1 >> 9) & 1u) ? fmaxf(e1.x * tB.z, e1.y * tB.w) : 0.f;
                afrA[1] = pkbf(p0, p1); afrA[3] = pkbf(p8, p9);
            }
            {
                float p0 = (h2 & 1u) ? fmaxf(e2.x * tA.x, e2.y * tA.y) : 0.f;
                float p1 = ((h2 >> 1) & 1u) ? fmaxf(e2.x * tA.z, e2.y * tA.w) : 0.f;
                float p8 = ((h2 >> 8) & 1u) ? fmaxf(e2.x * tB.x, e2.y * tB.y) : 0.f;
                float p9 = ((h2 >> 9) & 1u) ? fmaxf(e2.x * tB.z, e2.y * tB.w) : 0.f;
                afrB[0] = pkbf(p0, p1); afrB[2] = pkbf(p8, p9);
            }
            {
                float p0 = (h3 & 1u) ? fmaxf(e3.x * tA.x, e3.y * tA.y) : 0.f;
                float p1 = ((h3 >> 1) & 1u) ? fmaxf(e3.x * tA.z, e3.y * tA.w) : 0.f;
                float p8 = ((h3 >> 8) & 1u) ? fmaxf(e3.x * tB.x, e3.y * tB.y) : 0.f;
                float p9 = ((h3 >> 9) & 1u) ? fmaxf(e3.x * tB.z, e3.y * tB.w) : 0.f;
                afrB[1] = pkbf(p0, p1); afrB[3] = pkbf(p8, p9);
            }

#pragma unroll
            for (int n = 0; n < 8; n++) {
                const __nv_bfloat16* bp = &whs[b][8 * n + m][16 * s + 2 * k];
                unsigned b0 = *(const unsigned*)bp;
                unsigned b1 = *(const unsigned*)(bp + 8);
                mma16(accA[n], afrA, b0, b1);
                mma16(accB[n], afrB, b0, b1);
            }
            mma16(accA[8], afrA, ONESBF, ONESBF);
            mma16(accB[8], afrB, ONESBF, ONESBF);
        }

        if (t + 1 < T) {
            asm volatile("cp.async.wait_group 0;" ::: "memory");
            M0 = N0; M1 = N1; M2 = N2; M3 = N3;
        }
        __syncthreads();
    }

    const int slot = y;
    float* p0 = g_part + ((size_t)slot * 4096 + r0) * 64 + 2 * k;
    float* p1 = p0 + 8 * 64;
    float* p2 = p0 + 16 * 64;
    float* p3 = p0 + 24 * 64;
#pragma unroll
    for (int n = 0; n < 8; n++) {
        *(float2*)(p0 + 8 * n) = make_float2(accA[n][0], accA[n][1]);
        *(float2*)(p1 + 8 * n) = make_float2(accA[n][2], accA[n][3]);
        *(float2*)(p2 + 8 * n) = make_float2(accB[n][0], accB[n][1]);
        *(float2*)(p3 + 8 * n) = make_float2(accB[n][2], accB[n][3]);
    }
    if (k == 0) {
        g_denp[slot * 4096 + r0] = accA[8][0];
        g_denp[slot * 4096 + r0 + 8] = accA[8][2];
        g_denp[slot * 4096 + r0 + 16] = accB[8][0];
        g_denp[slot * 4096 + r0 + 24] = accB[8][2];
    }
}

// ---------------- kE: combine heads + out GEMM (bf16 mma) + quads + WhT ----------------
// smem layout (bytes): wb [64][264] bf16 @0 (33792), hc [32][264] bf16 @33792 (16896),
//                      whs [32][68] f32 @50688 (8704), dhs [32][4] f32 @59392 (512)
#define KE_SMEM 59904
extern __shared__ char smE[];
__global__ __launch_bounds__(256) void kE(const float* __restrict__ w_out,
                                          const float* __restrict__ a_out) {
    unsigned* wbw = (unsigned*)smE;               // [64][132] words
    unsigned* hcw = (unsigned*)(smE + 33792);     // [32][132] words
    float* whs = (float*)(smE + 50688);           // [32][68]
    float* dhs = (float*)(smE + 59392);           // [32][4]
    const int tid = threadIdx.x;
    const int i0 = blockIdx.x * 32;

    if (tid < 128) {
        int r = tid >> 2, h = tid & 3, row = i0 + r;
        dhs[r * 4 + h] =
            1.f / (g_denp[(2 * h) * 4096 + row] + g_denp[(2 * h + 1) * 4096 + row]);
    }
    // stage w_out -> bf16 transposed [n][k]
#pragma unroll
    for (int u = 0; u < 32; u++) {
        int e = tid + 256 * u;
        int n = e >> 7, kk = e & 127;
        wbw[n * 132 + kk] =
            pkbf(__ldg(w_out + (2 * kk) * 64 + n), __ldg(w_out + (2 * kk + 1) * 64 + n));
    }
    __syncthreads();

    // combine head partials -> hc bf16 [m][k]
#pragma unroll
    for (int u = 0; u < 16; u++) {
        int e = tid + 256 * u;
        int m = e >> 7, kk = e & 127;
        int kcol = 2 * kk, h = kcol >> 6, c = kcol & 63;
        int row = i0 + m;
        const float* pa = g_part + ((size_t)(2 * h) * 4096 + row) * 64 + c;
        float2 va = *(const float2*)pa;
        float2 vb = *(const float2*)(pa + 4096 * 64);
        float di = dhs[m * 4 + h];
        hcw[m * 132 + kk] = pkbf(elu1((va.x + vb.x) * di), elu1((va.y + vb.y) * di));
    }
    __syncthreads();

    // GEMM: warp = (mblk, nquad)
    const int wid = tid >> 5, lane = tid & 31;
    const int mblk = wid & 1, nq = wid >> 1;
    const int mrow = 16 * mblk + (lane >> 2), kq = lane & 3;
    float acc[2][4];
#pragma unroll
    for (int ni = 0; ni < 2; ni++)
#pragma unroll
        for (int u = 0; u < 4; u++) acc[ni][u] = 0.f;

#pragma unroll
    for (int ks = 0; ks < 16; ks++) {
        unsigned A[4];
        A[0] = hcw[mrow * 132 + 8 * ks + kq];
        A[1] = hcw[(mrow + 8) * 132 + 8 * ks + kq];
        A[2] = hcw[mrow * 132 + 8 * ks + kq + 4];
        A[3] = hcw[(mrow + 8) * 132 + 8 * ks + kq + 4];
#pragma unroll
        for (int ni = 0; ni < 2; ni++) {
            int n = 2 * nq + ni;
            unsigned b0 = wbw[(8 * n + (lane >> 2)) * 132 + 8 * ks + kq];
            unsigned b1 = wbw[(8 * n + (lane >> 2)) * 132 + 8 * ks + kq + 4];
            mma16(acc[ni], A, b0, b1);
        }
    }

    // write result to whs
#pragma unroll
    for (int ni = 0; ni < 2; ni++) {
        int col = 8 * (2 * nq + ni) + 2 * kq;
        *(float2*)&whs[mrow * 68 + col] = make_float2(acc[ni][0], acc[ni][1]);
        *(float2*)&whs[(mrow + 8) * 68 + col] = make_float2(acc[ni][2], acc[ni][3]);
    }
    __syncthreads();

    // layer-4 s,t quads
    {
        const int r = tid >> 3, g = tid & 7;
        float sp = 0.f, tp = 0.f;
#pragma unroll
        for (int u = 0; u < 8; u++) {
            int c = g * 8 + u;
            float v = whs[r * 68 + c];
            sp += v * __ldg(a_out + c);
            tp += v * __ldg(a_out + 64 + c);
        }
        sp += __shfl_xor_sync(0xffffffffu, sp, 1);
        sp += __shfl_xor_sync(0xffffffffu, sp, 2);
        sp += __shfl_xor_sync(0xffffffffu, sp, 4);
        tp += __shfl_xor_sync(0xffffffffu, tp, 1);
        tp += __shfl_xor_sync(0xffffffffu, tp, 2);
        tp += __shfl_xor_sync(0xffffffffu, tp, 4);
        if (g == 0) {
            g_sq2[4 * 4096 + i0 + r] = make_float2(__expf(sp), __expf(ALPHA * sp));
            g_tq2[4 * 4096 + i0 + r] = make_float2(__expf(tp), __expf(ALPHA * tp));
        }
    }

    // transposed bf16 WhT store
    {
        int col = tid >> 2, seg = tid & 3;
        float v[8];
#pragma unroll
        for (int q = 0; q < 8; q++) v[q] = whs[(seg * 8 + q) * 68 + col];
        uint4 pk;
        pk.x = pkbf(v[0], v[1]);
        pk.y = pkbf(v[2], v[3]);
        pk.z = pkbf(v[4], v[5]);
        pk.w = pkbf(v[6], v[7]);
        g_WhT4[(((size_t)(4 * 64 + col)) * 4096 + i0 + seg * 8) >> 3] = pk;
    }
}

// ---------------- kG: combine out-layer partials + residual + final linear + elu ----------------
__global__ __launch_bounds__(256) void kG(const float* __restrict__ outlin_w,
                                          const float* __restrict__ outlin_b,
                                          float* __restrict__ out) {
    __shared__ float vi[32 * 68];
    __shared__ float wt[64 * 68];
    __shared__ float dinv[32];
    const int tid = threadIdx.x;
    const int i0 = blockIdx.x * 32;

    if (tid < 32) {
        int row = i0 + tid;
        float ds = 0.f;
#pragma unroll
        for (int s = 0; s < 8; s++) ds += g_denp[s * 4096 + row];
        dinv[tid] = 1.f / ds;
    }
#pragma unroll
    for (int u = 0; u < 16; u++) {
        int idx = tid + 256 * u;
        int k2 = idx >> 6, k = idx & 63;
        wt[k * 68 + k2] = outlin_w[k2 * 64 + k];
    }
    __syncthreads();

#pragma unroll
    for (int u = 0; u < 2; u++) {
        int idx = tid + 256 * u;
        int r = idx >> 4, kq = (idx & 15) * 4;
        int row = i0 + r;
        float4 n = make_float4(0.f, 0.f, 0.f, 0.f);
#pragma unroll
        for (int s = 0; s < 8; s++) {
            float4 v = *(const float4*)&g_part[((size_t)s * 4096 + row) * 64 + kq];
            n.x += v.x; n.y += v.y; n.z += v.z; n.w += v.w;
        }
        float4 xa = *(const float4*)&g_xres[(size_t)row * 64 + kq];
        float di = dinv[r];
        xa.x += elu1(n.x * di);
        xa.y += elu1(n.y * di);
        xa.z += elu1(n.z * di);
        xa.w += elu1(n.w * di);
        *(float4*)&vi[r * 68 + kq] = xa;
    }
    __syncthreads();

    const int r = tid >> 3, g = tid & 7;
    float acc[8];
#pragma unroll
    for (int u = 0; u < 8; u++) acc[u] = 0.f;
#pragma unroll 8
    for (int k = 0; k < 64; k++) {
        float xv = vi[r * 68 + k];
        float4 w0 = *(float4*)&wt[k * 68 + g * 4];
        float4 w1 = *(float4*)&wt[k * 68 + 32 + g * 4];
        acc[0] += xv * w0.x; acc[1] += xv * w0.y;
        acc[2] += xv * w0.z; acc[3] += xv * w0.w;
        acc[4] += xv * w1.x; acc[5] += xv * w1.y;
        acc[6] += xv * w1.z; acc[7] += xv * w1.w;
    }
    float* dst = out + (size_t)(i0 + r) * 64;
    *(float4*)(dst + g * 4) = make_float4(
        elu1(acc[0] + outlin_b[g * 4 + 0]), elu1(acc[1] + outlin_b[g * 4 + 1]),
        elu1(acc[2] + outlin_b[g * 4 + 2]), elu1(acc[3] + outlin_b[g * 4 + 3]));
    *(float4*)(dst + 32 + g * 4) = make_float4(
        elu1(acc[4] + outlin_b[32 + g * 4 + 0]), elu1(acc[5] + outlin_b[32 + g * 4 + 1]),
        elu1(acc[6] + outlin_b[32 + g * 4 + 2]), elu1(acc[7] + outlin_b[32 + g * 4 + 3]));
}

// ---------------- launch ----------------
extern "C" void kernel_launch(void* const* d_in, const int* in_sizes, int n_in,
                              void* d_out, int out_size) {
    const float* x        = (const float*)d_in[0];
    const int*   adj      = (const int*)d_in[1];
    const float* w_heads  = (const float*)d_in[2];
    const float* a_heads  = (const float*)d_in[3];
    const float* w_out    = (const float*)d_in[4];
    const float* a_out    = (const float*)d_in[5];
    const float* lin_w    = (const float*)d_in[6];
    const float* lin_b    = (const float*)d_in[7];
    const float* outlin_w = (const float*)d_in[8];
    const float* outlin_b = (const float*)d_in[9];
    float* out = (float*)d_out;

    static int inited = 0;
    if (!inited) {
        cudaFuncSetAttribute(kE, cudaFuncAttributeMaxDynamicSharedMemorySize, KE_SMEM);
        inited = 1;
    }

    kP<<<4096, 256>>>(adj);
    kA<<<dim3(128, 5), 256>>>(x, w_heads, lin_w, lin_b, a_heads);
    kC<<<dim3(16, 8), 256>>>(0);             // 4 heads x 2 j-slices -> partials
    kE<<<128, 256, KE_SMEM>>>(w_out, a_out); // combine + out GEMM + quads + WhT
    kC<<<dim3(16, 8), 256>>>(1);             // out layer, 8 j-slices -> partials
    kG<<<128, 256>>>(outlin_w, outlin_b, out);
}